// round 3
// baseline (speedup 1.0000x reference)
#include <cuda_runtime.h>
#include <cuda_bf16.h>

// Problem dims (fixed by dataset)
#define BB 4
#define TT_ 512
#define UU 128
#define DD 512
#define VV 512

// text projection scratch: tp[b*U+u][v] = text@W^T + bias   (1 MB, L2-resident)
__device__ float g_tp[BB * UU * VV];

#define BAR_SYNC(id, n)   asm volatile("bar.sync %0, %1;"   :: "r"(id), "r"(n) : "memory")
#define BAR_ARRIVE(id, n) asm volatile("bar.arrive %0, %1;" :: "r"(id), "r"(n) : "memory")

// Named barrier IDs
#define FULL0   1
#define EMPTY0  3
#define MATHBAR 5

// ---------------------------------------------------------------------------
// Kernel 1: tp[m, v] = sum_d text[m, d] * W[v, d] + bias[v]
// 32x32 tiles, 128 threads, grid (16,16). Also writes the length tail.
// ---------------------------------------------------------------------------
__global__ __launch_bounds__(128)
void tp_kernel(const float* __restrict__ text,
               const float* __restrict__ Wm,
               const float* __restrict__ bias,
               const int* __restrict__ slen,
               const int* __restrict__ tlen,
               float* __restrict__ out)
{
    __shared__ float As[16][36];
    __shared__ float Ws[16][36];

    const int tid = threadIdx.x;
    const int n0 = blockIdx.x * 32;
    const int m0 = blockIdx.y * 32;

    const float* Ap = text + (size_t)m0 * DD;
    const float* Wp = Wm   + (size_t)n0 * DD;

    const int r = tid >> 2;      // 0..31
    const int c = tid & 3;       // 0..3
    const int tx = tid & 7;      // cols tx*4 .. +3
    const int ty = tid >> 3;     // rows ty*2, ty*2+1

    float acc[2][4] = {};

    for (int k0 = 0; k0 < DD; k0 += 16) {
        float4 a = *(const float4*)(Ap + (size_t)r * DD + k0 + c * 4);
        float4 w = *(const float4*)(Wp + (size_t)r * DD + k0 + c * 4);
        __syncthreads();
        As[c*4+0][r] = a.x; As[c*4+1][r] = a.y; As[c*4+2][r] = a.z; As[c*4+3][r] = a.w;
        Ws[c*4+0][r] = w.x; Ws[c*4+1][r] = w.y; Ws[c*4+2][r] = w.z; Ws[c*4+3][r] = w.w;
        __syncthreads();
#pragma unroll
        for (int kk = 0; kk < 16; kk++) {
            float2 av = *(const float2*)&As[kk][ty * 2];
            float4 wv = *(const float4*)&Ws[kk][tx * 4];
            acc[0][0] += av.x * wv.x; acc[0][1] += av.x * wv.y;
            acc[0][2] += av.x * wv.z; acc[0][3] += av.x * wv.w;
            acc[1][0] += av.y * wv.x; acc[1][1] += av.y * wv.y;
            acc[1][2] += av.y * wv.z; acc[1][3] += av.y * wv.w;
        }
    }

    float4 bv = *(const float4*)(bias + n0 + tx * 4);
#pragma unroll
    for (int rr = 0; rr < 2; rr++) {
        float4 o;
        o.x = acc[rr][0] + bv.x; o.y = acc[rr][1] + bv.y;
        o.z = acc[rr][2] + bv.z; o.w = acc[rr][3] + bv.w;
        *(float4*)(g_tp + (size_t)(m0 + ty * 2 + rr) * VV + n0 + tx * 4) = o;
    }

    // Length tail: outputs 1 and 2 flattened after logits, as float32.
    if (blockIdx.x == 0 && blockIdx.y == 0 && tid < 8) {
        size_t base = (size_t)BB * TT_ * UU * VV;
        if (tid < 4) out[base + tid] = (float)slen[tid];
        else         out[base + tid] = (float)tlen[tid - 4];
    }
}

// ---------------------------------------------------------------------------
// Kernel 2: fused sp-projection + broadcast-add, warp-specialized.
// Grid = 128 CTAs x 512 threads. Each CTA: 4 tiles of (32 bt x 64 v).
//   Tiles t = bid*4 + i; vt = t>>6 (v-strip constant per CTA), btt = t&63.
//   warps 0-7  (tid<256):  GEMM sp_tile = speech[bt0:+32] @ W[v0:+64]^T
//   warps 8-15 (tid>=256): out[bt, u, v] = sp_s + tp[b*U+u, v]  (1 MB/tile)
// Double-buffered sp_s; FULL/EMPTY named-barrier handoff.
// ---------------------------------------------------------------------------
__global__ __launch_bounds__(512, 1)
void fused_kernel(const float* __restrict__ speech,
                  const float* __restrict__ Wm,
                  float* __restrict__ out)
{
    __shared__ float As[2][16][36];   // A chunk: [k][m], double-buffered
    __shared__ float Ws[2][16][68];   // W chunk: [k][n]
    __shared__ float sp_s[2][32][64]; // sp tile, double-buffered

    const int tid = threadIdx.x;
    const int bid = blockIdx.x;

    if (tid < 256) {
        // ------------------------- MATH WARPS -------------------------
        const int tx = tid & 15;     // cols tx*4 .. +3 (of 64)
        const int ty = tid >> 4;     // rows ty*2, ty*2+1 (of 32)
        const int lr = tid >> 2;     // load row: 0..63
        const int lc = tid & 3;      // load k-subchunk

        for (int i = 0; i < 4; i++) {
            const int t   = bid * 4 + i;
            const int v0  = (t >> 6) * 64;
            const int bt0 = (t & 63) * 32;
            const float* Ap = speech + (size_t)bt0 * DD;
            const float* Wp = Wm     + (size_t)v0 * DD;

            float acc[2][4] = {};

            // Preload chunk 0 into buffer 0
            {
                float4 w = *(const float4*)(Wp + (size_t)lr * DD + lc * 4);
                Ws[0][lc*4+0][lr] = w.x; Ws[0][lc*4+1][lr] = w.y;
                Ws[0][lc*4+2][lr] = w.z; Ws[0][lc*4+3][lr] = w.w;
                if (tid < 128) {
                    float4 a = *(const float4*)(Ap + (size_t)lr * DD + lc * 4);
                    As[0][lc*4+0][lr] = a.x; As[0][lc*4+1][lr] = a.y;
                    As[0][lc*4+2][lr] = a.z; As[0][lc*4+3][lr] = a.w;
                }
            }
            BAR_SYNC(MATHBAR, 256);

            for (int kc = 0; kc < 32; kc++) {
                const int cur = kc & 1;
                float4 aN, wN;
                if (kc < 31) {
                    const int k0 = (kc + 1) * 16;
                    wN = *(const float4*)(Wp + (size_t)lr * DD + k0 + lc * 4);
                    if (tid < 128)
                        aN = *(const float4*)(Ap + (size_t)lr * DD + k0 + lc * 4);
                }
#pragma unroll
                for (int kk = 0; kk < 16; kk++) {
                    float2 av = *(const float2*)&As[cur][kk][ty * 2];
                    float4 wv = *(const float4*)&Ws[cur][kk][tx * 4];
                    acc[0][0] += av.x * wv.x; acc[0][1] += av.x * wv.y;
                    acc[0][2] += av.x * wv.z; acc[0][3] += av.x * wv.w;
                    acc[1][0] += av.y * wv.x; acc[1][1] += av.y * wv.y;
                    acc[1][2] += av.y * wv.z; acc[1][3] += av.y * wv.w;
                }
                if (kc < 31) {
                    const int nxt = cur ^ 1;
                    Ws[nxt][lc*4+0][lr] = wN.x; Ws[nxt][lc*4+1][lr] = wN.y;
                    Ws[nxt][lc*4+2][lr] = wN.z; Ws[nxt][lc*4+3][lr] = wN.w;
                    if (tid < 128) {
                        As[nxt][lc*4+0][lr] = aN.x; As[nxt][lc*4+1][lr] = aN.y;
                        As[nxt][lc*4+2][lr] = aN.z; As[nxt][lc*4+3][lr] = aN.w;
                    }
                    BAR_SYNC(MATHBAR, 256);
                }
            }

            // Hand tile to writers (wait for buffer to be free from tile i-2)
            if (i >= 2) BAR_SYNC(EMPTY0 + (i & 1), 512);
            const int b = i & 1;
            *(float4*)&sp_s[b][ty*2    ][tx*4] =
                make_float4(acc[0][0], acc[0][1], acc[0][2], acc[0][3]);
            *(float4*)&sp_s[b][ty*2 + 1][tx*4] =
                make_float4(acc[1][0], acc[1][1], acc[1][2], acc[1][3]);
            asm volatile("membar.cta;" ::: "memory");
            BAR_ARRIVE(FULL0 + (i & 1), 512);
        }
    } else {
        // ------------------------- WRITER WARPS -------------------------
        const int wtid = tid - 256;
        const int v4 = wtid & 15;    // float4 column (of 16)
        const int r  = wtid >> 4;    // rows r and r+16 (of 32)

        for (int i = 0; i < 4; i++) {
            const int t   = bid * 4 + i;
            const int v0  = (t >> 6) * 64;
            const int bt0 = (t & 63) * 32;
            const int bb  = bt0 >> 9;          // batch index

            BAR_SYNC(FULL0 + (i & 1), 512);
            const int b = i & 1;
            const float4 s0 = *(const float4*)&sp_s[b][r     ][v4 * 4];
            const float4 s1 = *(const float4*)&sp_s[b][r + 16][v4 * 4];

            const float4* tpp = (const float4*)(g_tp + (size_t)bb * UU * VV + v0) + v4;
            float4* p0 = (float4*)out + (size_t)(bt0 + r) * UU * (VV/4) + (v0 >> 2) + v4;
            float4* p1 = p0 + (size_t)16 * UU * (VV/4);

#pragma unroll 4
            for (int u = 0; u < UU; u++) {
                float4 tv = __ldg(tpp);
                float4 r0, r1;
                r0.x = s0.x + tv.x; r0.y = s0.y + tv.y;
                r0.z = s0.z + tv.z; r0.w = s0.w + tv.w;
                r1.x = s1.x + tv.x; r1.y = s1.y + tv.y;
                r1.z = s1.z + tv.z; r1.w = s1.w + tv.w;
                *p0 = r0;
                *p1 = r1;
                tpp += VV / 4;
                p0  += VV / 4;
                p1  += VV / 4;
            }
            if (i < 2) BAR_ARRIVE(EMPTY0 + (i & 1), 512);
        }
    }
}

extern "C" void kernel_launch(void* const* d_in, const int* in_sizes, int n_in,
                              void* d_out, int out_size)
{
    const float* speech = (const float*)d_in[0];
    const float* text   = (const float*)d_in[1];
    const float* Wm     = (const float*)d_in[2];
    const float* bias   = (const float*)d_in[3];
    const int*   slen   = (const int*)d_in[4];
    const int*   tlen   = (const int*)d_in[5];

    // Phase 1: text projection (+ bias) into g_tp, plus length tail
    tp_kernel<<<dim3(16, 16), 128>>>(text, Wm, bias, slen, tlen, (float*)d_out);

    // Phase 2: fused speech projection + broadcast add (warp-specialized)
    fused_kernel<<<128, 512>>>(speech, Wm, (float*)d_out);
}

// round 4
// speedup vs baseline: 1.3498x; 1.3498x over previous
#include <cuda_runtime.h>
#include <cuda_bf16.h>

// Problem dims (fixed by dataset)
#define BB 4
#define TT_ 512
#define UU 128
#define DD 512
#define VV 512

// text projection scratch: tp[b*U+u][v] = text@W^T + bias   (1 MB, L2-resident)
__device__ float g_tp[BB * UU * VV];

// ---------------------------------------------------------------------------
// Kernel 1: tp[m, v] = sum_d text[m, d] * W[v, d] + bias[v]
// 32x32 tiles, 128 threads, grid (16,16). Also writes the length tail.
// ---------------------------------------------------------------------------
__global__ __launch_bounds__(128)
void tp_kernel(const float* __restrict__ text,
               const float* __restrict__ Wm,
               const float* __restrict__ bias,
               const int* __restrict__ slen,
               const int* __restrict__ tlen,
               float* __restrict__ out)
{
    __shared__ float As[16][36];
    __shared__ float Ws[16][36];

    const int tid = threadIdx.x;
    const int n0 = blockIdx.x * 32;
    const int m0 = blockIdx.y * 32;

    const float* Ap = text + (size_t)m0 * DD;
    const float* Wp = Wm   + (size_t)n0 * DD;

    const int r = tid >> 2;      // 0..31
    const int c = tid & 3;       // 0..3
    const int tx = tid & 7;      // cols tx*4 .. +3
    const int ty = tid >> 3;     // rows ty*2, ty*2+1

    float acc[2][4] = {};

    for (int k0 = 0; k0 < DD; k0 += 16) {
        float4 a = *(const float4*)(Ap + (size_t)r * DD + k0 + c * 4);
        float4 w = *(const float4*)(Wp + (size_t)r * DD + k0 + c * 4);
        __syncthreads();
        As[c*4+0][r] = a.x; As[c*4+1][r] = a.y; As[c*4+2][r] = a.z; As[c*4+3][r] = a.w;
        Ws[c*4+0][r] = w.x; Ws[c*4+1][r] = w.y; Ws[c*4+2][r] = w.z; Ws[c*4+3][r] = w.w;
        __syncthreads();
#pragma unroll
        for (int kk = 0; kk < 16; kk++) {
            float2 av = *(const float2*)&As[kk][ty * 2];
            float4 wv = *(const float4*)&Ws[kk][tx * 4];
            acc[0][0] += av.x * wv.x; acc[0][1] += av.x * wv.y;
            acc[0][2] += av.x * wv.z; acc[0][3] += av.x * wv.w;
            acc[1][0] += av.y * wv.x; acc[1][1] += av.y * wv.y;
            acc[1][2] += av.y * wv.z; acc[1][3] += av.y * wv.w;
        }
    }

    float4 bv = *(const float4*)(bias + n0 + tx * 4);
#pragma unroll
    for (int rr = 0; rr < 2; rr++) {
        float4 o;
        o.x = acc[rr][0] + bv.x; o.y = acc[rr][1] + bv.y;
        o.z = acc[rr][2] + bv.z; o.w = acc[rr][3] + bv.w;
        *(float4*)(g_tp + (size_t)(m0 + ty * 2 + rr) * VV + n0 + tx * 4) = o;
    }

    // Length tail: outputs 1 and 2 flattened after logits, as float32.
    if (blockIdx.x == 0 && blockIdx.y == 0 && tid < 8) {
        size_t base = (size_t)BB * TT_ * UU * VV;
        if (tid < 4) out[base + tid] = (float)slen[tid];
        else         out[base + tid] = (float)tlen[tid - 4];
    }
}

// ---------------------------------------------------------------------------
// Kernel 2: fused sp-projection + broadcast-add. NO warp specialization.
// 512 CTAs x 256 threads; each CTA owns one (32 bt x 64 v) tile:
//   Phase A: sp_tile = speech[bt0:+32,:] @ W[v0:+64,:]^T   (into smem)
//   Phase B: out[bt, u, v0:+64] = sp_tile + tp[b*U+u, v0:+64]  (1 MB stream)
// Overlap happens ACROSS CTAs: drain-phase warps stall on store
// backpressure while compute-phase warps of co-resident CTAs issue FFMAs.
// ---------------------------------------------------------------------------
__global__ __launch_bounds__(256, 5)
void sp_add_kernel(const float* __restrict__ speech,
                   const float* __restrict__ Wm,
                   float* __restrict__ out)
{
    __shared__ float As[16][36];     // [k][m] chunk
    __shared__ float Ws[16][68];     // [k][n] chunk
    __shared__ float sp_s[32][64];   // finished sp tile

    const int tid = threadIdx.x;
    const int t   = blockIdx.x;            // 0..511
    const int v0  = (t & 7) * 64;          // 8 v-blocks; adjacent CTAs share bt rows
    const int bt0 = (t >> 3) * 32;         // 64 bt-blocks

    const float* Ap = speech + (size_t)bt0 * DD;
    const float* Wp = Wm     + (size_t)v0 * DD;

    // ---------------- Phase A: GEMM into sp_s ----------------
    {
        const int lr = tid >> 2;    // 0..63
        const int lc = tid & 3;     // 0..3
        const int tx = tid & 15;    // cols tx*4 .. +3 (of 64)
        const int ty = tid >> 4;    // rows ty*2, ty*2+1 (of 32)

        float acc[2][4] = {};

        for (int k0 = 0; k0 < DD; k0 += 16) {
            float4 w = *(const float4*)(Wp + (size_t)lr * DD + k0 + lc * 4);
            float4 a;
            if (tid < 128)
                a = *(const float4*)(Ap + (size_t)lr * DD + k0 + lc * 4);
            __syncthreads();
            Ws[lc*4+0][lr] = w.x; Ws[lc*4+1][lr] = w.y;
            Ws[lc*4+2][lr] = w.z; Ws[lc*4+3][lr] = w.w;
            if (tid < 128) {
                As[lc*4+0][lr] = a.x; As[lc*4+1][lr] = a.y;
                As[lc*4+2][lr] = a.z; As[lc*4+3][lr] = a.w;
            }
            __syncthreads();
#pragma unroll
            for (int kk = 0; kk < 16; kk++) {
                float2 av = *(const float2*)&As[kk][ty * 2];
                float4 wv = *(const float4*)&Ws[kk][tx * 4];
                acc[0][0] += av.x * wv.x; acc[0][1] += av.x * wv.y;
                acc[0][2] += av.x * wv.z; acc[0][3] += av.x * wv.w;
                acc[1][0] += av.y * wv.x; acc[1][1] += av.y * wv.y;
                acc[1][2] += av.y * wv.z; acc[1][3] += av.y * wv.w;
            }
        }

        *(float4*)&sp_s[ty*2    ][tx*4] =
            make_float4(acc[0][0], acc[0][1], acc[0][2], acc[0][3]);
        *(float4*)&sp_s[ty*2 + 1][tx*4] =
            make_float4(acc[1][0], acc[1][1], acc[1][2], acc[1][3]);
    }
    __syncthreads();

    // ---------------- Phase B: stream out = sp + tp ----------------
    {
        const int v4 = tid & 15;    // float4 column within 64-v strip
        const int rr = tid >> 4;    // rows rr and rr+16 (of 32)
        const int b  = bt0 >> 9;    // batch index

        const float4 s0 = *(const float4*)&sp_s[rr     ][v4 * 4];
        const float4 s1 = *(const float4*)&sp_s[rr + 16][v4 * 4];

        const float4* tpp = (const float4*)(g_tp + (size_t)b * UU * VV + v0) + v4;
        float4* p0 = (float4*)out + ((size_t)(bt0 + rr) * UU) * (VV/4) + (v0 >> 2) + v4;
        float4* p1 = p0 + (size_t)16 * UU * (VV/4);

#pragma unroll 4
        for (int u = 0; u < UU; u++) {
            float4 tv = __ldg(tpp);
            float4 r0, r1;
            r0.x = s0.x + tv.x; r0.y = s0.y + tv.y;
            r0.z = s0.z + tv.z; r0.w = s0.w + tv.w;
            r1.x = s1.x + tv.x; r1.y = s1.y + tv.y;
            r1.z = s1.z + tv.z; r1.w = s1.w + tv.w;
            __stcs(p0, r0);
            __stcs(p1, r1);
            tpp += VV / 4;
            p0  += VV / 4;
            p1  += VV / 4;
        }
    }
}

extern "C" void kernel_launch(void* const* d_in, const int* in_sizes, int n_in,
                              void* d_out, int out_size)
{
    const float* speech = (const float*)d_in[0];
    const float* text   = (const float*)d_in[1];
    const float* Wm     = (const float*)d_in[2];
    const float* bias   = (const float*)d_in[3];
    const int*   slen   = (const int*)d_in[4];
    const int*   tlen   = (const int*)d_in[5];

    // Phase 1: text projection (+ bias) into g_tp, plus length tail
    tp_kernel<<<dim3(16, 16), 128>>>(text, Wm, bias, slen, tlen, (float*)d_out);

    // Phase 2: fused speech projection + broadcast add
    sp_add_kernel<<<512, 256>>>(speech, Wm, (float*)d_out);
}